// round 1
// baseline (speedup 1.0000x reference)
#include <cuda_runtime.h>
#include <cstdint>

#define N_NODES 50000
#define LDA 144          // padded K for layer-1 fused GEMM: [h0(68) | deginv*agg1(68)] -> pad 144
#define GBLK 782         // ceil(N_NODES/64)

// ---------------- scratch (static __device__, no allocation) ----------------
__device__ float g_A[N_NODES * LDA];      // layer-1 GEMM input, stride 144
__device__ float g_agg1[N_NODES * 68];    // scatter target layer 1 (cols 66,67 stay 0)
__device__ float g_h1[N_NODES * 128];     // relu output layer 1
__device__ float g_uv[N_NODES * 128];     // cols 0..63 = h1@W2_nbr, cols 64..127 = h1@W2_root
__device__ float g_agg2[N_NODES * 64];    // scatter target layer 2
__device__ float g_h2[N_NODES * 64];      // final embeddings
__device__ float g_deginv[N_NODES];
__device__ int   g_deg[N_NODES];
__device__ float g_W1[144 * 128];         // rows 0-65 W1_root, 66-67 zero, 68-133 W1_nbr, 134-143 zero
__device__ float g_W2[128 * 128];         // cols 0-63 W2_nbr, cols 64-127 W2_root

// ---------------- helpers ----------------
__device__ __forceinline__ void red4(float* p, float4 v) {
    asm volatile("red.global.add.v4.f32 [%0], {%1,%2,%3,%4};"
                 :: "l"(p), "f"(v.x), "f"(v.y), "f"(v.z), "f"(v.w) : "memory");
}

// ---------------- kernels ----------------
__global__ void k_zero() {
    int t0 = blockIdx.x * blockDim.x + threadIdx.x;
    int stride = gridDim.x * blockDim.x;
    for (int i = t0; i < N_NODES * 68; i += stride) g_agg1[i] = 0.0f;
    for (int i = t0; i < N_NODES * 64; i += stride) g_agg2[i] = 0.0f;
    for (int i = t0; i < N_NODES; i += stride) g_deg[i] = 0;
}

__global__ void k_prepw(const float* __restrict__ W1r, const float* __restrict__ W1n,
                        const float* __restrict__ W2r, const float* __restrict__ W2n) {
    int t0 = blockIdx.x * blockDim.x + threadIdx.x;
    int stride = gridDim.x * blockDim.x;
    for (int i = t0; i < 144 * 128; i += stride) {
        int r = i >> 7, c = i & 127;
        float v = 0.0f;
        if (r < 66) v = W1r[r * 128 + c];
        else if (r >= 68 && r < 134) v = W1n[(r - 68) * 128 + c];
        g_W1[i] = v;
    }
    for (int i = t0; i < 128 * 128; i += stride) {
        int r = i >> 7, c = i & 127;
        g_W2[i] = (c < 64) ? W2n[r * 64 + c] : W2r[r * 64 + (c - 64)];
    }
}

__global__ void k_deg(const int* __restrict__ dst, int E) {
    int i = blockIdx.x * blockDim.x + threadIdx.x;
    if (i < E) atomicAdd(&g_deg[dst[i]], 1);
}

__global__ void k_deginv() {
    int i = blockIdx.x * blockDim.x + threadIdx.x;
    if (i < N_NODES) g_deginv[i] = 1.0f / fmaxf((float)g_deg[i], 1.0f);
}

// A cols 0-67 = concat(x,pos,0,0); cols 136-143 = 0
__global__ void k_buildA1(const float* __restrict__ x, const float* __restrict__ pos) {
    int i = blockIdx.x * blockDim.x + threadIdx.x;
    if (i >= N_NODES * 76) return;
    int n = i / 76, c = i % 76;
    int col = (c < 68) ? c : (c + 68);
    float v = 0.0f;
    if (col < 64) v = x[n * 64 + col];
    else if (col < 66) v = pos[n * 2 + (col - 64)];
    g_A[n * LDA + col] = v;
}

// scatter layer 1: 4 threads/edge, 17 float4 chunks (68 floats)
__global__ void k_scatter1(const int* __restrict__ src, const int* __restrict__ dst, int E) {
    int t = blockIdx.x * blockDim.x + threadIdx.x;
    int e = t >> 2, lane = t & 3;
    if (e >= E) return;
    int s = src[e], d = dst[e];
    const float4* sp = (const float4*)(g_A + (size_t)s * LDA);
    float* dp = g_agg1 + (size_t)d * 68;
    #pragma unroll
    for (int c = 0; c < 5; c++) {
        int ch = lane + 4 * c;
        if (ch < 17) {
            float4 v = __ldg(&sp[ch]);
            red4(dp + ch * 4, v);
        }
    }
}

// A cols 68-135 = deginv * agg1
__global__ void k_buildA2() {
    int i = blockIdx.x * blockDim.x + threadIdx.x;
    if (i >= N_NODES * 68) return;
    int n = i / 68, c = i % 68;
    g_A[n * LDA + 68 + c] = g_agg1[i] * g_deginv[n];
}

// GEMM: C[M,128] = A[M,K] @ B[K,128] (+bias, relu). MODE 0: layer1. MODE 1: layer2.
template <int MODE>
__global__ __launch_bounds__(256) void k_gemm(const float* __restrict__ bias) {
    const int K   = (MODE == 0) ? 144 : 128;
    const int lda = (MODE == 0) ? 144 : 128;
    const float* __restrict__ A = (MODE == 0) ? g_A : g_h1;
    const float* __restrict__ B = (MODE == 0) ? g_W1 : g_W2;
    float* __restrict__ C       = (MODE == 0) ? g_h1 : g_uv;

    __shared__ float As[16][65];
    __shared__ float Bs[16][128];

    int tid = threadIdx.x;
    int block_row = blockIdx.x * 64;
    int arow = tid >> 2, acol4 = tid & 3;           // A tile load: 64 rows x 4 float4
    int brow = tid >> 5, bcol4 = tid & 31;          // B tile load: 8(+8) rows x 32 float4
    int ty = tid >> 4, tx = tid & 15;               // 16x16 compute grid
    int a_grow = min(block_row + arow, N_NODES - 1);

    float acc[4][8];
    #pragma unroll
    for (int i = 0; i < 4; i++)
        #pragma unroll
        for (int j = 0; j < 8; j++) acc[i][j] = 0.0f;

    for (int k0 = 0; k0 < K; k0 += 16) {
        float4 av  = *(const float4*)(A + (size_t)a_grow * lda + k0 + acol4 * 4);
        float4 bv0 = *(const float4*)(B + (size_t)(k0 + brow) * 128 + bcol4 * 4);
        float4 bv1 = *(const float4*)(B + (size_t)(k0 + brow + 8) * 128 + bcol4 * 4);
        __syncthreads();
        As[acol4 * 4 + 0][arow] = av.x;
        As[acol4 * 4 + 1][arow] = av.y;
        As[acol4 * 4 + 2][arow] = av.z;
        As[acol4 * 4 + 3][arow] = av.w;
        *(float4*)&Bs[brow][bcol4 * 4] = bv0;
        *(float4*)&Bs[brow + 8][bcol4 * 4] = bv1;
        __syncthreads();
        #pragma unroll
        for (int kk = 0; kk < 16; kk++) {
            float a[4], b[8];
            #pragma unroll
            for (int i = 0; i < 4; i++) a[i] = As[kk][ty * 4 + i];
            #pragma unroll
            for (int j = 0; j < 8; j++) b[j] = Bs[kk][tx + 16 * j];
            #pragma unroll
            for (int i = 0; i < 4; i++)
                #pragma unroll
                for (int j = 0; j < 8; j++) acc[i][j] += a[i] * b[j];
        }
    }

    #pragma unroll
    for (int i = 0; i < 4; i++) {
        int r = block_row + ty * 4 + i;
        if (r >= N_NODES) break;
        #pragma unroll
        for (int j = 0; j < 8; j++) {
            int c = tx + 16 * j;
            float v = acc[i][j];
            if (MODE == 0) {
                v += bias[c];
                v = fmaxf(v, 0.0f);
            }
            C[(size_t)r * 128 + c] = v;
        }
    }
}

// scatter layer 2: 4 threads/edge, 16 float4 chunks from g_uv cols 0-63
__global__ void k_scatter2(const int* __restrict__ src, const int* __restrict__ dst, int E) {
    int t = blockIdx.x * blockDim.x + threadIdx.x;
    int e = t >> 2, lane = t & 3;
    if (e >= E) return;
    int s = src[e], d = dst[e];
    const float4* sp = (const float4*)(g_uv + (size_t)s * 128);
    float* dp = g_agg2 + (size_t)d * 64;
    #pragma unroll
    for (int c = 0; c < 4; c++) {
        int ch = lane + 4 * c;
        float4 v = __ldg(&sp[ch]);
        red4(dp + ch * 4, v);
    }
}

// h2 = r2 + deginv*agg2 + b2  (r2 = g_uv cols 64-127)
__global__ void k_final(const float* __restrict__ b2) {
    int i = blockIdx.x * blockDim.x + threadIdx.x;
    if (i >= N_NODES * 16) return;
    int n = i >> 4, c = i & 15;
    float4 r = ((const float4*)g_uv)[n * 32 + 16 + c];
    float4 a = ((const float4*)g_agg2)[n * 16 + c];
    float4 b = ((const float4*)b2)[c];
    float di = g_deginv[n];
    float4 o;
    o.x = r.x + a.x * di + b.x;
    o.y = r.y + a.y * di + b.y;
    o.z = r.z + a.z * di + b.z;
    o.w = r.w + a.w * di + b.w;
    ((float4*)g_h2)[n * 16 + c] = o;
}

// out[e] = dot(h2[src], h2[dst]); 4 threads/edge
__global__ void k_edge(const int* __restrict__ src, const int* __restrict__ dst, int E,
                       float* __restrict__ out) {
    int t = blockIdx.x * blockDim.x + threadIdx.x;
    int e = t >> 2, lane = t & 3;
    if (e >= E) return;
    int s = src[e], d = dst[e];
    const float4* sp = (const float4*)(g_h2 + (size_t)s * 64);
    const float4* dp = (const float4*)(g_h2 + (size_t)d * 64);
    float acc = 0.0f;
    #pragma unroll
    for (int c = 0; c < 4; c++) {
        int ch = lane + 4 * c;
        float4 a = __ldg(&sp[ch]);
        float4 b = __ldg(&dp[ch]);
        acc += a.x * b.x + a.y * b.y + a.z * b.z + a.w * b.w;
    }
    acc += __shfl_xor_sync(0xffffffffu, acc, 1);
    acc += __shfl_xor_sync(0xffffffffu, acc, 2);
    if (lane == 0) out[e] = acc;
}

// ---------------- launch ----------------
extern "C" void kernel_launch(void* const* d_in, const int* in_sizes, int n_in,
                              void* d_out, int out_size) {
    const float* x   = (const float*)d_in[0];
    const float* pos = (const float*)d_in[1];
    const int*   ei  = (const int*)d_in[2];
    const float* W1r = (const float*)d_in[3];
    const float* W1n = (const float*)d_in[4];
    const float* b1  = (const float*)d_in[5];
    const float* W2r = (const float*)d_in[6];
    const float* W2n = (const float*)d_in[7];
    const float* b2  = (const float*)d_in[8];
    float* out = (float*)d_out;

    int E = in_sizes[2] / 2;
    const int* src = ei;
    const int* dst = ei + E;

    k_zero<<<512, 256>>>();
    k_prepw<<<80, 256>>>(W1r, W1n, W2r, W2n);
    k_deg<<<(E + 255) / 256, 256>>>(dst, E);
    k_deginv<<<(N_NODES + 255) / 256, 256>>>();
    k_buildA1<<<(N_NODES * 76 + 255) / 256, 256>>>(x, pos);
    k_scatter1<<<(4 * E + 255) / 256, 256>>>(src, dst, E);
    k_buildA2<<<(N_NODES * 68 + 255) / 256, 256>>>();
    k_gemm<0><<<GBLK, 256>>>(b1);
    k_gemm<1><<<GBLK, 256>>>(b1);
    k_scatter2<<<(4 * E + 255) / 256, 256>>>(src, dst, E);
    k_final<<<(N_NODES * 16 + 255) / 256, 256>>>(b2);
    k_edge<<<(4 * E + 255) / 256, 256>>>(src, dst, E, out);
}

// round 2
// speedup vs baseline: 1.3116x; 1.3116x over previous
#include <cuda_runtime.h>
#include <cstdint>

#define N_NODES 50000
#define EMAX 1600000
#define LDA 144
#define GBLK 782         // ceil(N_NODES/64)
#define SB 512
#define NB 98            // ceil(N_NODES/512)

// ---------------- scratch (static __device__, no allocation) ----------------
__device__ float g_A[N_NODES * LDA];      // layer-1 GEMM input, stride 144 (cols 134..143 stay 0 forever)
__device__ float g_h1[N_NODES * 128];     // relu output layer 1
__device__ float g_uv[N_NODES * 128];     // cols 0..63 = h1@W2_nbr, cols 64..127 = h1@W2_root
__device__ float g_h2[N_NODES * 64];      // final embeddings
__device__ float g_deginv[N_NODES];
__device__ int   g_deg[N_NODES];
__device__ int   g_cur[N_NODES];
__device__ int   g_rowptr[N_NODES + 1];
__device__ int   g_bsum[NB];
__device__ int   g_boff[NB];
__device__ int   g_csr[EMAX];             // src ids bucketed by dst
__device__ float g_W1[144 * 128];
__device__ float g_W2[128 * 128];

// ---------------- small kernels ----------------
__global__ void k_zero() {
    int t0 = blockIdx.x * blockDim.x + threadIdx.x;
    int stride = gridDim.x * blockDim.x;
    for (int i = t0; i < N_NODES; i += stride) { g_deg[i] = 0; g_cur[i] = 0; }
}

__global__ void k_prepw(const float* __restrict__ W1r, const float* __restrict__ W1n,
                        const float* __restrict__ W2r, const float* __restrict__ W2n) {
    int t0 = blockIdx.x * blockDim.x + threadIdx.x;
    int stride = gridDim.x * blockDim.x;
    for (int i = t0; i < 144 * 128; i += stride) {
        int r = i >> 7, c = i & 127;
        float v = 0.0f;
        if (r < 66) v = W1r[r * 128 + c];
        else if (r >= 68 && r < 134) v = W1n[(r - 68) * 128 + c];
        g_W1[i] = v;
    }
    for (int i = t0; i < 128 * 128; i += stride) {
        int r = i >> 7, c = i & 127;
        g_W2[i] = (c < 64) ? W2n[r * 64 + c] : W2r[r * 64 + (c - 64)];
    }
}

__global__ void k_deg(const int* __restrict__ dst, int E) {
    int i = blockIdx.x * blockDim.x + threadIdx.x;
    if (i < E) atomicAdd(&g_deg[dst[i]], 1);
}

// block-wise exclusive scan of deg -> rowptr (partial), block totals
__global__ void k_scan1() {
    __shared__ int s[SB];
    int tid = threadIdx.x;
    int i = blockIdx.x * SB + tid;
    int v = (i < N_NODES) ? g_deg[i] : 0;
    s[tid] = v;
    __syncthreads();
    #pragma unroll
    for (int off = 1; off < SB; off <<= 1) {
        int t = (tid >= off) ? s[tid - off] : 0;
        __syncthreads();
        s[tid] += t;
        __syncthreads();
    }
    if (i < N_NODES) g_rowptr[i] = s[tid] - v;
    if (tid == SB - 1) g_bsum[blockIdx.x] = s[tid];
}

__global__ void k_scan2() {
    if (threadIdx.x == 0 && blockIdx.x == 0) {
        int run = 0;
        for (int b = 0; b < NB; b++) { g_boff[b] = run; run += g_bsum[b]; }
    }
}

__global__ void k_scan3(int E) {
    int i = blockIdx.x * blockDim.x + threadIdx.x;
    if (i < N_NODES) {
        g_rowptr[i] += g_boff[i / SB];
        g_deginv[i] = 1.0f / fmaxf((float)g_deg[i], 1.0f);
    }
    if (i == 0) g_rowptr[N_NODES] = E;
}

__global__ void k_fillcsr(const int* __restrict__ src, const int* __restrict__ dst, int E) {
    int e = blockIdx.x * blockDim.x + threadIdx.x;
    if (e >= E) return;
    int d = dst[e];
    int ofs = atomicAdd(&g_cur[d], 1);
    g_csr[g_rowptr[d] + ofs] = src[e];
}

// A cols 0..67 = concat(x, pos, 0, 0)
__global__ void k_buildA1(const float* __restrict__ x, const float* __restrict__ pos) {
    int i = blockIdx.x * blockDim.x + threadIdx.x;
    if (i >= N_NODES * 68) return;
    int n = i / 68, c = i % 68;
    float v = 0.0f;
    if (c < 64) v = x[n * 64 + c];
    else if (c < 66) v = pos[n * 2 + (c - 64)];
    g_A[(size_t)n * LDA + c] = v;
}

// ---------------- gather-side aggregation, layer 1 ----------------
// one warp per node; lane owns float2 of x-row; lane 0 also accumulates pos
__global__ __launch_bounds__(256) void k_agg1(const float* __restrict__ x,
                                              const float* __restrict__ pos) {
    int gt = blockIdx.x * blockDim.x + threadIdx.x;
    int w = gt >> 5, lane = gt & 31;
    if (w >= N_NODES) return;
    int start = g_rowptr[w], end = g_rowptr[w + 1];
    float ax = 0.f, ay = 0.f, px = 0.f, py = 0.f;
    const float2* x2 = (const float2*)x;
    const float2* p2 = (const float2*)pos;
    int i = start;
    for (; i + 32 <= end; i += 32) {
        int eid = g_csr[i + lane];
        #pragma unroll
        for (int j = 0; j < 32; j++) {
            int s = __shfl_sync(0xffffffffu, eid, j);
            float2 v = __ldg(x2 + (size_t)s * 32 + lane);
            ax += v.x; ay += v.y;
            if (lane == 0) { float2 p = __ldg(p2 + s); px += p.x; py += p.y; }
        }
    }
    if (i < end) {
        int m = end - i;
        int eid = (i + lane < end) ? g_csr[i + lane] : 0;
        for (int j = 0; j < m; j++) {
            int s = __shfl_sync(0xffffffffu, eid, j);
            float2 v = __ldg(x2 + (size_t)s * 32 + lane);
            ax += v.x; ay += v.y;
            if (lane == 0) { float2 p = __ldg(p2 + s); px += p.x; py += p.y; }
        }
    }
    float di = g_deginv[w];
    float* rowp = g_A + (size_t)w * LDA;
    rowp[68 + lane * 2]     = ax * di;
    rowp[68 + lane * 2 + 1] = ay * di;
    if (lane == 0) { rowp[132] = px * di; rowp[133] = py * di; }
}

// ---------------- GEMM (same as R0) ----------------
template <int MODE>
__global__ __launch_bounds__(256) void k_gemm(const float* __restrict__ bias) {
    const int K   = (MODE == 0) ? 144 : 128;
    const int lda = (MODE == 0) ? 144 : 128;
    const float* __restrict__ A = (MODE == 0) ? g_A : g_h1;
    const float* __restrict__ B = (MODE == 0) ? g_W1 : g_W2;
    float* __restrict__ C       = (MODE == 0) ? g_h1 : g_uv;

    __shared__ float As[16][65];
    __shared__ float Bs[16][128];

    int tid = threadIdx.x;
    int block_row = blockIdx.x * 64;
    int arow = tid >> 2, acol4 = tid & 3;
    int brow = tid >> 5, bcol4 = tid & 31;
    int ty = tid >> 4, tx = tid & 15;
    int a_grow = min(block_row + arow, N_NODES - 1);

    float acc[4][8];
    #pragma unroll
    for (int i = 0; i < 4; i++)
        #pragma unroll
        for (int j = 0; j < 8; j++) acc[i][j] = 0.0f;

    for (int k0 = 0; k0 < K; k0 += 16) {
        float4 av  = *(const float4*)(A + (size_t)a_grow * lda + k0 + acol4 * 4);
        float4 bv0 = *(const float4*)(B + (size_t)(k0 + brow) * 128 + bcol4 * 4);
        float4 bv1 = *(const float4*)(B + (size_t)(k0 + brow + 8) * 128 + bcol4 * 4);
        __syncthreads();
        As[acol4 * 4 + 0][arow] = av.x;
        As[acol4 * 4 + 1][arow] = av.y;
        As[acol4 * 4 + 2][arow] = av.z;
        As[acol4 * 4 + 3][arow] = av.w;
        *(float4*)&Bs[brow][bcol4 * 4] = bv0;
        *(float4*)&Bs[brow + 8][bcol4 * 4] = bv1;
        __syncthreads();
        #pragma unroll
        for (int kk = 0; kk < 16; kk++) {
            float a[4], b[8];
            #pragma unroll
            for (int i = 0; i < 4; i++) a[i] = As[kk][ty * 4 + i];
            #pragma unroll
            for (int j = 0; j < 8; j++) b[j] = Bs[kk][tx + 16 * j];
            #pragma unroll
            for (int i = 0; i < 4; i++)
                #pragma unroll
                for (int j = 0; j < 8; j++) acc[i][j] += a[i] * b[j];
        }
    }

    #pragma unroll
    for (int i = 0; i < 4; i++) {
        int r = block_row + ty * 4 + i;
        if (r >= N_NODES) break;
        #pragma unroll
        for (int j = 0; j < 8; j++) {
            int c = tx + 16 * j;
            float v = acc[i][j];
            if (MODE == 0) {
                v += bias[c];
                v = fmaxf(v, 0.0f);
            }
            C[(size_t)r * 128 + c] = v;
        }
    }
}

// ---------------- gather-side aggregation, layer 2 (+ fused final) ----------------
__global__ __launch_bounds__(256) void k_agg2(const float* __restrict__ b2) {
    int gt = blockIdx.x * blockDim.x + threadIdx.x;
    int w = gt >> 5, lane = gt & 31;
    if (w >= N_NODES) return;
    int start = g_rowptr[w], end = g_rowptr[w + 1];
    float ax = 0.f, ay = 0.f;
    const float2* uv2 = (const float2*)g_uv;   // row = 64 float2; cols 0..63 -> first 32 float2
    int i = start;
    for (; i + 32 <= end; i += 32) {
        int eid = g_csr[i + lane];
        #pragma unroll
        for (int j = 0; j < 32; j++) {
            int s = __shfl_sync(0xffffffffu, eid, j);
            float2 v = __ldg(uv2 + (size_t)s * 64 + lane);
            ax += v.x; ay += v.y;
        }
    }
    if (i < end) {
        int m = end - i;
        int eid = (i + lane < end) ? g_csr[i + lane] : 0;
        for (int j = 0; j < m; j++) {
            int s = __shfl_sync(0xffffffffu, eid, j);
            float2 v = __ldg(uv2 + (size_t)s * 64 + lane);
            ax += v.x; ay += v.y;
        }
    }
    float di = g_deginv[w];
    float rx = g_uv[(size_t)w * 128 + 64 + lane * 2];
    float ry = g_uv[(size_t)w * 128 + 64 + lane * 2 + 1];
    g_h2[(size_t)w * 64 + lane * 2]     = rx + ax * di + b2[lane * 2];
    g_h2[(size_t)w * 64 + lane * 2 + 1] = ry + ay * di + b2[lane * 2 + 1];
}

// out[e] = dot(h2[src], h2[dst]); 4 threads/edge
__global__ void k_edge(const int* __restrict__ src, const int* __restrict__ dst, int E,
                       float* __restrict__ out) {
    int t = blockIdx.x * blockDim.x + threadIdx.x;
    int e = t >> 2, lane = t & 3;
    if (e >= E) return;
    int s = src[e], d = dst[e];
    const float4* sp = (const float4*)(g_h2 + (size_t)s * 64);
    const float4* dp = (const float4*)(g_h2 + (size_t)d * 64);
    float acc = 0.0f;
    #pragma unroll
    for (int c = 0; c < 4; c++) {
        int ch = lane + 4 * c;
        float4 a = __ldg(&sp[ch]);
        float4 b = __ldg(&dp[ch]);
        acc += a.x * b.x + a.y * b.y + a.z * b.z + a.w * b.w;
    }
    acc += __shfl_xor_sync(0xffffffffu, acc, 1);
    acc += __shfl_xor_sync(0xffffffffu, acc, 2);
    if (lane == 0) out[e] = acc;
}

// ---------------- launch ----------------
extern "C" void kernel_launch(void* const* d_in, const int* in_sizes, int n_in,
                              void* d_out, int out_size) {
    const float* x   = (const float*)d_in[0];
    const float* pos = (const float*)d_in[1];
    const int*   ei  = (const int*)d_in[2];
    const float* W1r = (const float*)d_in[3];
    const float* W1n = (const float*)d_in[4];
    const float* b1  = (const float*)d_in[5];
    const float* W2r = (const float*)d_in[6];
    const float* W2n = (const float*)d_in[7];
    const float* b2  = (const float*)d_in[8];
    float* out = (float*)d_out;

    int E = in_sizes[2] / 2;
    const int* src = ei;
    const int* dst = ei + E;

    k_zero<<<64, 256>>>();
    k_prepw<<<80, 256>>>(W1r, W1n, W2r, W2n);
    k_deg<<<(E + 255) / 256, 256>>>(dst, E);
    k_scan1<<<NB, SB>>>();
    k_scan2<<<1, 32>>>();
    k_scan3<<<(N_NODES + 255) / 256, 256>>>(E);
    k_fillcsr<<<(E + 255) / 256, 256>>>(src, dst, E);
    k_buildA1<<<(N_NODES * 68 + 255) / 256, 256>>>(x, pos);
    k_agg1<<<(N_NODES * 32 + 255) / 256, 256>>>(x, pos);
    k_gemm<0><<<GBLK, 256>>>(b1);
    k_gemm<1><<<GBLK, 256>>>(b1);
    k_agg2<<<(N_NODES * 32 + 255) / 256, 256>>>(b2);
    k_edge<<<(4 * E + 255) / 256, 256>>>(src, dst, E, out);
}